// round 6
// baseline (speedup 1.0000x reference)
#include <cuda_runtime.h>
#include <stdint.h>

// SpatialTransformer_with_disp: trilinear warp, B=2, D=160, H=192, W=224, C=1.
// Output = concat(warped [B*D*H*W], flow [B*D*H*W*3]) as float32.
//
// R6 (= R5 resubmit; rounds 3-5 all lost to broker timeouts, design unbenched).
// R2 profile: L1TEX-wavefront-bound (86.4%), DRAM 38.5%. Strategy:
//  - pair-duplicated volume dup[k]=(v[k], v[k+1 clamped]) -> 4 LDG.64 gathers
//    instead of 8 scalar LDGs (halves L1 wavefront bill),
//  - flow read once, staged via smem, copy written from same registers,
//  - __stwt on write-once outputs to keep L2 for the gather working set.

constexpr int Dd = 160;
constexpr int Hh = 192;
constexpr int Ww = 224;                 // threads per block = one W-row
constexpr int ROW_F = Ww * 3;           // 672 flow floats per row
constexpr int ROW_F4 = ROW_F / 4;       // 168 float4 per row
constexpr long NV = 2L * Dd * Hh * Ww;  // 13,762,560 voxels

// 110 MB device scratch: x-pair duplicated volume.
__device__ float2 g_dup[NV];

// Each thread produces two adjacent float2 outputs (one float4 store).
__global__ __launch_bounds__(Ww / 2) void build_pairs_kernel(
    const float* __restrict__ vol)
{
    const int t = threadIdx.x;       // 0..111 -> x = 2t
    const int y = blockIdx.x;        // 0..191
    const int z = blockIdx.y;        // 0..159
    const int b = blockIdx.z;        // 0..1
    const int x = 2 * t;
    const long idx = ((long)((b * Dd + z) * Hh + y)) * Ww + x;

    const float a = __ldg(&vol[idx]);
    const float c = __ldg(&vol[idx + 1]);
    const float e = __ldg(&vol[idx + (x + 2 < Ww ? 2 : 1)]);  // clamp within row
    float4 o;
    o.x = a; o.y = c;     // dup[x]   = (v[x],   v[x+1])
    o.z = c; o.w = e;     // dup[x+1] = (v[x+1], v[x+2 clamped])
    *reinterpret_cast<float4*>(&g_dup[idx]) = o;   // normal store: re-read next kernel
}

__device__ __forceinline__ void axis_interp(float loc, float maxl,
                                            int& i0, float& wlo) {
    float cl = fminf(fmaxf(loc, 0.0f), maxl);
    float l0 = fminf(fmaxf(floorf(loc), 0.0f), maxl);
    float l1 = fminf(l0 + 1.0f, maxl);
    i0 = (int)l0;
    wlo = l1 - cl;   // neurite convention: low-corner weight = loc1 - clipped_loc
}

__global__ __launch_bounds__(Ww) void warp_fused_kernel(
    const float* __restrict__ flow,   // [B, D, H, W, 3]
    float* __restrict__ warped,       // [B, D, H, W]        (= out)
    float* __restrict__ flow_copy,    // [B, D, H, W, 3]     (= out + nv)
    int do_copy)
{
    __shared__ float s[ROW_F];

    const int x = threadIdx.x;       // 0..223
    const int y = blockIdx.x;        // 0..191
    const int z = blockIdx.y;        // 0..159
    const int b = blockIdx.z;        // 0..1

    const long row = (long)((b * Dd + z) * Hh + y);   // row index in [B*D*H]
    const long vox = row * Ww + x;
    const long fbase = row * ROW_F;

    // Stage this row's flow through smem with coalesced float4 loads; the same
    // registers produce the verbatim copy write (flow read from DRAM once).
    if (x < ROW_F4) {
        const float4 v = __ldg(((const float4*)(flow + fbase)) + x);
        ((float4*)s)[x] = v;
        if (do_copy) __stwt(((float4*)(flow_copy + fbase)) + x, v);  // write-once
    }
    __syncthreads();

    const float fz = s[3 * x + 0];
    const float fy = s[3 * x + 1];
    const float fx = s[3 * x + 2];

    int i0z, i0y, i0x;
    float wz0, wy0, wx0;
    axis_interp((float)z + fz, (float)(Dd - 1), i0z, wz0);
    axis_interp((float)y + fy, (float)(Hh - 1), i0y, wy0);
    axis_interp((float)x + fx, (float)(Ww - 1), i0x, wx0);
    const int i1z = min(i0z + 1, Dd - 1);
    const int i1y = min(i0y + 1, Hh - 1);
    const float wz1 = 1.0f - wz0;
    const float wy1 = 1.0f - wy0;
    const float wx1 = 1.0f - wx0;

    const float2* db = g_dup + (long)b * Dd * Hh * Ww;

    // 4 independent LDG.64 gathers (x-pair fused into the dup layout)
    const float2 p00 = __ldg(&db[((long)i0z * Hh + i0y) * Ww + i0x]);
    const float2 p01 = __ldg(&db[((long)i0z * Hh + i1y) * Ww + i0x]);
    const float2 p10 = __ldg(&db[((long)i1z * Hh + i0y) * Ww + i0x]);
    const float2 p11 = __ldg(&db[((long)i1z * Hh + i1y) * Ww + i0x]);

    const float c00 = p00.x * wx0 + p00.y * wx1;
    const float c01 = p01.x * wx0 + p01.y * wx1;
    const float c10 = p10.x * wx0 + p10.y * wx1;
    const float c11 = p11.x * wx0 + p11.y * wx1;

    const float c0 = c00 * wy0 + c01 * wy1;
    const float c1 = c10 * wy0 + c11 * wy1;

    __stwt(&warped[vox], c0 * wz0 + c1 * wz1);   // write-once
}

extern "C" void kernel_launch(void* const* d_in, const int* in_sizes, int n_in,
                              void* d_out, int out_size) {
    const float* vol  = (const float*)d_in[0];
    const float* flow = (const float*)d_in[1];
    float* out = (float*)d_out;

    const long nv = (long)in_sizes[0];  // B*D*H*W*C  = 13,762,560
    const long nf = (long)in_sizes[1];  // B*D*H*W*3  = 41,287,680

    const int do_copy = ((long)out_size >= nv + nf) ? 1 : 0;
    float* flow_copy = do_copy ? (out + nv) : out;

    dim3 grid(Hh, Dd, 2);
    build_pairs_kernel<<<grid, dim3(Ww / 2, 1, 1)>>>(vol);
    warp_fused_kernel<<<grid, dim3(Ww, 1, 1)>>>(flow, out, flow_copy, do_copy);
}

// round 13
// speedup vs baseline: 1.2106x; 1.2106x over previous
#include <cuda_runtime.h>
#include <cuda_fp16.h>
#include <stdint.h>

// SpatialTransformer_with_disp: trilinear warp, B=2, D=160, H=192, W=224, C=1.
// Output = concat(warped [B*D*H*W], flow [B*D*H*W*3]) as float32.
//
// R13 (= R7..R12 resubmit; six broker timeouts in a row, design unbenched).
// Measured: R2 scalar gathers 131.2us (L1 86%); R6 float2 pair-dup 180.4us
// (gather bytes doubled -> L2 regression). Half2 pair-dup dominates both axes:
// 4 LDG.32 gathers/voxel (half the instructions of R2) and 16B/voxel gather
// payload (half the bytes of R2), 55MB table (same footprint as raw vol).
// fp16 quantization of vol adds ~1.5e-4 rel err, well under the 1e-3 gate.

constexpr int Dd = 160;
constexpr int Hh = 192;
constexpr int Ww = 224;                 // threads per block = one W-row
constexpr int ROW_F = Ww * 3;           // 672 flow floats per row
constexpr int ROW_F4 = ROW_F / 4;       // 168 float4 per row
constexpr long NV = 2L * Dd * Hh * Ww;  // 13,762,560 voxels

// 55 MB device scratch: x-pair duplicated volume in fp16.
__device__ __half2 g_dup[NV];

// Each thread produces two adjacent half2 entries (one 8B store).
__global__ __launch_bounds__(Ww / 2) void build_pairs_kernel(
    const float* __restrict__ vol)
{
    const int t = threadIdx.x;       // 0..111 -> x = 2t
    const int y = blockIdx.x;        // 0..191
    const int z = blockIdx.y;        // 0..159
    const int b = blockIdx.z;        // 0..1
    const int x = 2 * t;
    const long idx = ((long)((b * Dd + z) * Hh + y)) * Ww + x;

    const float a = __ldg(&vol[idx]);
    const float c = __ldg(&vol[idx + 1]);
    const float e = __ldg(&vol[idx + (x + 2 < Ww ? 2 : 1)]);  // clamp within row

    const __half ha = __float2half_rn(a);
    const __half hc = __float2half_rn(c);
    const __half he = __float2half_rn(e);

    __half2 pair0 = __halves2half2(ha, hc);  // dup[x]   = (v[x],   v[x+1])
    __half2 pair1 = __halves2half2(hc, he);  // dup[x+1] = (v[x+1], v[x+2 clamped])

    uint2 o;
    o.x = *reinterpret_cast<uint32_t*>(&pair0);
    o.y = *reinterpret_cast<uint32_t*>(&pair1);
    *reinterpret_cast<uint2*>(&g_dup[idx]) = o;  // 8B aligned (idx even)
}

__device__ __forceinline__ void axis_interp(float loc, float maxl,
                                            int& i0, float& wlo) {
    float cl = fminf(fmaxf(loc, 0.0f), maxl);
    float l0 = fminf(fmaxf(floorf(loc), 0.0f), maxl);
    float l1 = fminf(l0 + 1.0f, maxl);
    i0 = (int)l0;
    wlo = l1 - cl;   // neurite convention: low-corner weight = loc1 - clipped_loc
}

__global__ __launch_bounds__(Ww) void warp_fused_kernel(
    const float* __restrict__ flow,   // [B, D, H, W, 3]
    float* __restrict__ warped,       // [B, D, H, W]        (= out)
    float* __restrict__ flow_copy,    // [B, D, H, W, 3]     (= out + nv)
    int do_copy)
{
    __shared__ float s[ROW_F];

    const int x = threadIdx.x;       // 0..223
    const int y = blockIdx.x;        // 0..191
    const int z = blockIdx.y;        // 0..159
    const int b = blockIdx.z;        // 0..1

    const long row = (long)((b * Dd + z) * Hh + y);   // row index in [B*D*H]
    const long vox = row * Ww + x;
    const long fbase = row * ROW_F;

    // Stage this row's flow through smem with coalesced float4 loads; the same
    // registers produce the verbatim copy write (flow read from DRAM once).
    if (x < ROW_F4) {
        const float4 v = __ldg(((const float4*)(flow + fbase)) + x);
        ((float4*)s)[x] = v;
        if (do_copy) __stwt(((float4*)(flow_copy + fbase)) + x, v);  // write-once
    }
    __syncthreads();

    const float fz = s[3 * x + 0];
    const float fy = s[3 * x + 1];
    const float fx = s[3 * x + 2];

    int i0z, i0y, i0x;
    float wz0, wy0, wx0;
    axis_interp((float)z + fz, (float)(Dd - 1), i0z, wz0);
    axis_interp((float)y + fy, (float)(Hh - 1), i0y, wy0);
    axis_interp((float)x + fx, (float)(Ww - 1), i0x, wx0);
    const int i1z = min(i0z + 1, Dd - 1);
    const int i1y = min(i0y + 1, Hh - 1);
    const float wz1 = 1.0f - wz0;
    const float wy1 = 1.0f - wy0;
    const float wx1 = 1.0f - wx0;

    const __half2* db = g_dup + (long)b * Dd * Hh * Ww;

    // 4 independent LDG.32 gathers (x-pair packed as half2)
    const __half2 h00 = __ldg(&db[((long)i0z * Hh + i0y) * Ww + i0x]);
    const __half2 h01 = __ldg(&db[((long)i0z * Hh + i1y) * Ww + i0x]);
    const __half2 h10 = __ldg(&db[((long)i1z * Hh + i0y) * Ww + i0x]);
    const __half2 h11 = __ldg(&db[((long)i1z * Hh + i1y) * Ww + i0x]);

    const float2 p00 = __half22float2(h00);
    const float2 p01 = __half22float2(h01);
    const float2 p10 = __half22float2(h10);
    const float2 p11 = __half22float2(h11);

    const float c00 = p00.x * wx0 + p00.y * wx1;
    const float c01 = p01.x * wx0 + p01.y * wx1;
    const float c10 = p10.x * wx0 + p10.y * wx1;
    const float c11 = p11.x * wx0 + p11.y * wx1;

    const float c0 = c00 * wy0 + c01 * wy1;
    const float c1 = c10 * wy0 + c11 * wy1;

    __stwt(&warped[vox], c0 * wz0 + c1 * wz1);   // write-once
}

extern "C" void kernel_launch(void* const* d_in, const int* in_sizes, int n_in,
                              void* d_out, int out_size) {
    const float* vol  = (const float*)d_in[0];
    const float* flow = (const float*)d_in[1];
    float* out = (float*)d_out;

    const long nv = (long)in_sizes[0];  // B*D*H*W*C  = 13,762,560
    const long nf = (long)in_sizes[1];  // B*D*H*W*3  = 41,287,680

    const int do_copy = ((long)out_size >= nv + nf) ? 1 : 0;
    float* flow_copy = do_copy ? (out + nv) : out;

    dim3 grid(Hh, Dd, 2);
    build_pairs_kernel<<<grid, dim3(Ww / 2, 1, 1)>>>(vol);
    warp_fused_kernel<<<grid, dim3(Ww, 1, 1)>>>(flow, out, flow_copy, do_copy);
}

// round 16
// speedup vs baseline: 1.4003x; 1.1567x over previous
#include <cuda_runtime.h>
#include <cuda_fp16.h>
#include <stdint.h>

// SpatialTransformer_with_disp: trilinear warp, B=2, D=160, H=192, W=224, C=1.
// Output = concat(warped [B*D*H*W], flow [B*D*H*W*3]) as float32.
//
// R16 (= R14/R15 resubmit; both lost to broker timeouts).
// R13 measured: warp kernel 115.6us (half2 gather win confirmed; L1 86->66%),
// build pass 33.5us (bad streaming shape) sank the total to 149.1us.
// Fixes: (1) build = float4-in / uint4-out streaming, 256-thr blocks;
// (2) warp kernel processes 2 voxels/thread (rows z and z+80) to double
// outstanding gathers (latency-bound: issue 43%, no unit >67%).

constexpr int Dd = 160;
constexpr int Hh = 192;
constexpr int Ww = 224;
constexpr int ROW_F = Ww * 3;           // 672 flow floats per row
constexpr int ROW_F4 = ROW_F / 4;       // 168 float4 per row
constexpr long NV = 2L * Dd * Hh * Ww;  // 13,762,560 voxels
constexpr int G_PER_ROW = Ww / 4;       // 56 float4 groups per vol row
constexpr long N4 = NV / 4;             // 3,440,640 groups

// 55 MB device scratch: x-pair duplicated volume in fp16.
__device__ __half2 g_dup[NV];

// Streaming build: one float4 (4 voxels) in -> 4 half2 pairs (uint4) out.
__global__ __launch_bounds__(256) void build_pairs_kernel(
    const float* __restrict__ vol)
{
    const long g = (long)blockIdx.x * 256 + threadIdx.x;
    if (g >= N4) return;
    const int xg = (int)(g % G_PER_ROW);          // group index within row
    const long base = g * 4;

    const float4 a = __ldg((const float4*)(vol + base));
    const float nxt = (xg == G_PER_ROW - 1) ? a.w : __ldg(vol + base + 4);

    const __half h0 = __float2half_rn(a.x);
    const __half h1 = __float2half_rn(a.y);
    const __half h2 = __float2half_rn(a.z);
    const __half h3 = __float2half_rn(a.w);
    const __half h4 = __float2half_rn(nxt);

    __half2 p0 = __halves2half2(h0, h1);
    __half2 p1 = __halves2half2(h1, h2);
    __half2 p2 = __halves2half2(h2, h3);
    __half2 p3 = __halves2half2(h3, h4);

    uint4 o;
    o.x = *reinterpret_cast<uint32_t*>(&p0);
    o.y = *reinterpret_cast<uint32_t*>(&p1);
    o.z = *reinterpret_cast<uint32_t*>(&p2);
    o.w = *reinterpret_cast<uint32_t*>(&p3);
    *reinterpret_cast<uint4*>(&g_dup[base]) = o;   // 16B aligned, coalesced
}

__device__ __forceinline__ void axis_interp(float loc, float maxl,
                                            int& i0, float& wlo) {
    float cl = fminf(fmaxf(loc, 0.0f), maxl);
    float l0 = fminf(fmaxf(floorf(loc), 0.0f), maxl);
    float l1 = fminf(l0 + 1.0f, maxl);
    i0 = (int)l0;
    wlo = l1 - cl;   // neurite convention: low-corner weight = loc1 - clipped_loc
}

__device__ __forceinline__ float warp_one_voxel(
    const __half2* __restrict__ db, const float* s, int x, int y, int z)
{
    const float fz = s[3 * x + 0];
    const float fy = s[3 * x + 1];
    const float fx = s[3 * x + 2];

    int i0z, i0y, i0x;
    float wz0, wy0, wx0;
    axis_interp((float)z + fz, (float)(Dd - 1), i0z, wz0);
    axis_interp((float)y + fy, (float)(Hh - 1), i0y, wy0);
    axis_interp((float)x + fx, (float)(Ww - 1), i0x, wx0);
    const int i1z = min(i0z + 1, Dd - 1);
    const int i1y = min(i0y + 1, Hh - 1);

    const __half2 h00 = __ldg(&db[((long)i0z * Hh + i0y) * Ww + i0x]);
    const __half2 h01 = __ldg(&db[((long)i0z * Hh + i1y) * Ww + i0x]);
    const __half2 h10 = __ldg(&db[((long)i1z * Hh + i0y) * Ww + i0x]);
    const __half2 h11 = __ldg(&db[((long)i1z * Hh + i1y) * Ww + i0x]);

    const float wz1 = 1.0f - wz0, wy1 = 1.0f - wy0, wx1 = 1.0f - wx0;
    const float2 p00 = __half22float2(h00);
    const float2 p01 = __half22float2(h01);
    const float2 p10 = __half22float2(h10);
    const float2 p11 = __half22float2(h11);

    const float c00 = p00.x * wx0 + p00.y * wx1;
    const float c01 = p01.x * wx0 + p01.y * wx1;
    const float c10 = p10.x * wx0 + p10.y * wx1;
    const float c11 = p11.x * wx0 + p11.y * wx1;
    const float c0 = c00 * wy0 + c01 * wy1;
    const float c1 = c10 * wy0 + c11 * wy1;
    return c0 * wz0 + c1 * wz1;
}

// 2 voxels per thread: rows (y, z) and (y, z+80) of the same batch.
__global__ __launch_bounds__(Ww) void warp_fused_kernel(
    const float* __restrict__ flow,   // [B, D, H, W, 3]
    float* __restrict__ warped,       // [B, D, H, W]        (= out)
    float* __restrict__ flow_copy,    // [B, D, H, W, 3]     (= out + nv)
    int do_copy)
{
    __shared__ float s[2 * ROW_F];

    const int x  = threadIdx.x;      // 0..223
    const int y  = blockIdx.x;       // 0..191
    const int z0 = blockIdx.y;       // 0..79
    const int z1 = z0 + Dd / 2;      // 80..159
    const int b  = blockIdx.z;       // 0..1

    const long row0 = (long)((b * Dd + z0) * Hh + y);
    const long row1 = (long)((b * Dd + z1) * Hh + y);

    // Stage both rows' flow (336 float4 groups) with coalesced loads; the
    // same registers produce the verbatim copy writes.
    #pragma unroll
    for (int k = 0; k < 2; k++) {
        const int g = x + k * Ww;            // 0..447
        if (g < 2 * ROW_F4) {
            const int r = g / ROW_F4;        // 0 or 1
            const int o = g - r * ROW_F4;
            const long fb = (r ? row1 : row0) * ROW_F;
            const float4 v = __ldg(((const float4*)(flow + fb)) + o);
            ((float4*)s)[g < ROW_F4 ? o : ROW_F4 + o] = v;
            if (do_copy) __stwt(((float4*)(flow_copy + fb)) + o, v);
        }
    }
    __syncthreads();

    const __half2* db = g_dup + (long)b * Dd * Hh * Ww;

    // Two independent voxel computations -> 8 outstanding gathers.
    const float r0 = warp_one_voxel(db, s,         x, y, z0);
    const float r1 = warp_one_voxel(db, s + ROW_F, x, y, z1);

    __stwt(&warped[row0 * Ww + x], r0);
    __stwt(&warped[row1 * Ww + x], r1);
}

extern "C" void kernel_launch(void* const* d_in, const int* in_sizes, int n_in,
                              void* d_out, int out_size) {
    const float* vol  = (const float*)d_in[0];
    const float* flow = (const float*)d_in[1];
    float* out = (float*)d_out;

    const long nv = (long)in_sizes[0];  // B*D*H*W*C  = 13,762,560
    const long nf = (long)in_sizes[1];  // B*D*H*W*3  = 41,287,680

    const int do_copy = ((long)out_size >= nv + nf) ? 1 : 0;
    float* flow_copy = do_copy ? (out + nv) : out;

    const int bblocks = (int)((N4 + 255) / 256);
    build_pairs_kernel<<<bblocks, 256>>>(vol);

    dim3 grid(Hh, Dd / 2, 2);
    warp_fused_kernel<<<grid, dim3(Ww, 1, 1)>>>(flow, out, flow_copy, do_copy);
}